// round 12
// baseline (speedup 1.0000x reference)
#include <cuda_runtime.h>
#include <cstdint>

#define V_NODES   1000000
#define N_GRAPHS  50000
#define NODE_DIM  128
#define HIDDEN    128
#define GDIM      64
#define NT_TILES  7813

// ---------------- scratch ----------------
__device__ __align__(256) float g_Z1[(size_t)N_GRAPHS * HIDDEN];
__device__ __align__(256) float g_cnt[N_GRAPHS];
__device__ __align__(256) uint2 g_Wp[256 * 68];   // W1/W2 interleaved, tf32 bit-pairs (w[k], w[k+4]), stride 68
__device__ int g_is64;

// ---------------- helpers ----------------
__device__ __forceinline__ unsigned f2tf(float f) {
    unsigned u;
    asm("cvt.rna.tf32.f32 %0, %1;" : "=r"(u) : "f"(f));
    return u;
}

__device__ __forceinline__ void mma_tf32(float& c0, float& c1, float& c2, float& c3,
                                         unsigned a0, unsigned a1, unsigned a2, unsigned a3,
                                         unsigned b0, unsigned b1) {
    asm volatile(
        "mma.sync.aligned.m16n8k8.row.col.f32.tf32.tf32.f32 "
        "{%0,%1,%2,%3},{%4,%5,%6,%7},{%8,%9},{%0,%1,%2,%3};"
        : "+f"(c0), "+f"(c1), "+f"(c2), "+f"(c3)
        : "r"(a0), "r"(a1), "r"(a2), "r"(a3), "r"(b0), "r"(b1));
}

__device__ __forceinline__ void red4(float* p, float4 v) {
    asm volatile("red.global.add.v4.f32 [%0], {%1,%2,%3,%4};"
                 :: "l"(p), "f"(v.x), "f"(v.y), "f"(v.z), "f"(v.w) : "memory");
}

__device__ __forceinline__ float sigm(float x) { return 1.0f / (1.0f + __expf(-x)); }

__device__ __forceinline__ unsigned s2u(const void* p) {
    return (unsigned)__cvta_generic_to_shared(p);
}

__device__ __forceinline__ void cp16(unsigned dst, const void* src, unsigned sz) {
    asm volatile("cp.async.cg.shared.global [%0], [%1], 16, %2;"
                 :: "r"(dst), "l"(src), "r"(sz));
}
__device__ __forceinline__ void cp_commit() {
    asm volatile("cp.async.commit_group;");
}
template <int N>
__device__ __forceinline__ void cp_wait() {
    asm volatile("cp.async.wait_group %0;" :: "n"(N));
}

// ---------------- kernel 0: zero + dtype detect + W pre-convert (paired) ----------------
__global__ void k_init(const unsigned* __restrict__ n2g_words,
                       const float* __restrict__ W1, const float* __restrict__ W2) {
    if (blockIdx.x == 0) {
        __shared__ int nz;
        if (threadIdx.x == 0) nz = 0;
        __syncthreads();
        unsigned acc = 0;
        #pragma unroll
        for (int q = 0; q < 4; ++q)
            acc |= n2g_words[2 * (threadIdx.x * 4 + q) + 1];   // idx <= 2047
        if (acc != 0u) atomicOr(&nz, 1);
        __syncthreads();
        if (threadIdx.x == 0) g_is64 = (nz == 0) ? 1 : 0;
    }
    size_t i = (size_t)blockIdx.x * blockDim.x + threadIdx.x;
    size_t stride = (size_t)gridDim.x * blockDim.x;

    // W pairs: row r (r=2j -> W1[j], r=2j+1 -> W2[j]); entry (kb,k') = (w[kb*8+k'], w[kb*8+k'+4])
    for (size_t k = i; k < 256 * 64; k += stride) {
        int r = (int)(k >> 6), t = (int)(k & 63);
        int kb = t >> 2, kp = t & 3;
        const float* src = (r & 1) ? W2 : W1;
        int j = r >> 1;
        g_Wp[r * 68 + t] = make_uint2(f2tf(src[j * 128 + kb * 8 + kp]),
                                      f2tf(src[j * 128 + kb * 8 + kp + 4]));
    }

    float4* z = reinterpret_cast<float4*>(g_Z1);
    const size_t n4 = (size_t)N_GRAPHS * HIDDEN / 4;
    for (size_t k = i; k < n4; k += stride) z[k] = make_float4(0.f, 0.f, 0.f, 0.f);
    for (size_t k = i; k < N_GRAPHS; k += stride) g_cnt[k] = 0.f;
}

// ---------------- pad kernels: steer ncu capture (launch #4 = k_nodes) ----------------
__global__ void k_pad() {}

// ---------------- kernel: node MLP (gated) + per-node scatter, split-N ----------------
// blockIdx = tile*2 + half. Each CTA: 128 nodes x 128 N-cols (64 hidden j, lin1+lin2).
// 256 thr = 8 warps, 4(m) x 2(n), warp tile 32x64. W-half resident (uint2 pairs,
// LDS.64). 2-stage X cp.async pipeline (2 syncs/chunk). 107.5KB smem -> 2 CTA/SM:
// sibling CTA's mma overlaps this CTA's barriers/epilogue/scatter.
#define WT_U2H  (128 * 68)               // 8704 uint2 = 69632 B
#define WT_FLH  (WT_U2H * 2)             // float units
#define XSTG_FL (128 * 36)               // one X stage (18432 B)
#define HS_FL   (128 * 68)               // gated half (34816 B), aliases 2 X stages
#define SMEM_NODES_FL (WT_FLH + 2*XSTG_FL + 64 + 64 + 128)
#define SMEM_NODES_BYTES (SMEM_NODES_FL * 4)   // 107,520 B

__global__ __launch_bounds__(256, 2)
void k_nodes(const float* __restrict__ x, const void* __restrict__ n2g,
             const float* __restrict__ b1, const float* __restrict__ b2) {
    extern __shared__ float smem[];
    const uint2* WT2 = reinterpret_cast<const uint2*>(smem);   // [128*68]
    float* XS  = smem + WT_FLH;           // [2][128*36]
    float* HS  = smem + WT_FLH;           // [128*68] aliases X stages after drain
    float* B1S = smem + WT_FLH + 2 * XSTG_FL;
    float* B2S = B1S + 64;
    int*   GID = reinterpret_cast<int*>(B2S + 64);

    const int tid = threadIdx.x;
    const int lane = tid & 31;
    const int wid = tid >> 5;             // 0..7
    const int wm = wid >> 1;              // 0..3 -> m base wm*32
    const int wn = wid & 1;               // 0..1 -> n base wn*64
    const int tile = blockIdx.x >> 1;
    const int half = blockIdx.x & 1;
    const int node0 = tile * 128;
    const int is64 = g_is64;

    // group 0: resident W half (4352 x 16B)
    const char* wsrc = reinterpret_cast<const char*>(g_Wp + half * WT_U2H);
    #pragma unroll
    for (int p = 0; p < 17; ++p) {
        int idx = p * 256 + tid;
        cp16(s2u(reinterpret_cast<const char*>(smem) + idx * 16), wsrc + idx * 16, 16u);
    }
    cp_commit();

    auto issueX = [&](int kc, int buf) {
        float* XSb = XS + buf * XSTG_FL;
        #pragma unroll
        for (int p = 0; p < 4; ++p) {
            int idx = p * 256 + tid;
            int r = idx >> 3, c4 = idx & 7;
            int node = node0 + r;
            unsigned sz = (node < V_NODES) ? 16u : 0u;
            int nc = (node < V_NODES) ? node : (V_NODES - 1);
            cp16(s2u(XSb + r * 36 + c4 * 4),
                 x + (size_t)nc * NODE_DIM + kc * 32 + c4 * 4, sz);
        }
        cp_commit();
    };

    issueX(0, 0);
    issueX(1, 1);

    // bias half + gids while copies fly
    if (tid < 64)        B1S[tid]      = b1[half * 64 + tid];
    else if (tid < 128)  B2S[tid - 64] = b2[half * 64 + tid - 64];
    if (tid < 128) {
        int node = node0 + tid;
        int g = -1;
        if (node < V_NODES) {
            g = is64 ? (int)reinterpret_cast<const long long*>(n2g)[node]
                     : reinterpret_cast<const int*>(n2g)[node];
            if (half == 0) atomicAdd(&g_cnt[g], 1.0f);   // count once per node
        }
        GID[tid] = g;
    }

    float c[2][8][4];
    #pragma unroll
    for (int mi = 0; mi < 2; ++mi)
        #pragma unroll
        for (int ni = 0; ni < 8; ++ni)
            #pragma unroll
            for (int q = 0; q < 4; ++q) c[mi][ni][q] = 0.f;

    const int ro = lane >> 2;
    const int col0 = lane & 3;

    #pragma unroll
    for (int kc = 0; kc < 4; ++kc) {
        if (kc < 3) cp_wait<1>(); else cp_wait<0>();
        __syncthreads();                  // chunk kc (and W) visible

        const float* XSf = XS + (kc & 1) * XSTG_FL;
        #pragma unroll
        for (int ks = 0; ks < 4; ++ks) {
            const int co = ks * 8 + col0;
            unsigned a[2][4];
            #pragma unroll
            for (int mi = 0; mi < 2; ++mi) {
                int rb = wm * 32 + mi * 16;
                a[mi][0] = f2tf(XSf[(rb + ro) * 36 + co]);
                a[mi][1] = f2tf(XSf[(rb + ro + 8) * 36 + co]);
                a[mi][2] = f2tf(XSf[(rb + ro) * 36 + co + 4]);
                a[mi][3] = f2tf(XSf[(rb + ro + 8) * 36 + co + 4]);
            }
            const int kb4 = (kc * 4 + ks) * 4 + col0;
            #pragma unroll
            for (int ni = 0; ni < 8; ++ni) {
                int nr = wn * 64 + ni * 8 + ro;
                uint2 wv = WT2[nr * 68 + kb4];          // LDS.64: (w[co], w[co+4])
                mma_tf32(c[0][ni][0], c[0][ni][1], c[0][ni][2], c[0][ni][3],
                         a[0][0], a[0][1], a[0][2], a[0][3], wv.x, wv.y);
                mma_tf32(c[1][ni][0], c[1][ni][1], c[1][ni][2], c[1][ni][3],
                         a[1][0], a[1][1], a[1][2], a[1][3], wv.x, wv.y);
            }
        }

        __syncthreads();                  // all reads of stage kc&1 complete
        if (kc + 2 <= 3) issueX(kc + 2, kc & 1);
    }

    // epilogue: gate -> HS half (C col pairs: even=lin1[j], odd=lin2[j])
    #pragma unroll
    for (int ni = 0; ni < 8; ++ni) {
        int j = wn * 32 + ni * 4 + col0;   // local hidden 0..63 (pairs of cols)
        float bb1 = B1S[j], bb2 = B2S[j];
        int r = wm * 32 + ro;
        HS[r * 68 + j]        = (c[0][ni][0] + bb1) * sigm(c[0][ni][1] + bb2);
        HS[(r + 8) * 68 + j]  = (c[0][ni][2] + bb1) * sigm(c[0][ni][3] + bb2);
        HS[(r + 16) * 68 + j] = (c[1][ni][0] + bb1) * sigm(c[1][ni][1] + bb2);
        HS[(r + 24) * 68 + j] = (c[1][ni][2] + bb1) * sigm(c[1][ni][3] + bb2);
    }
    __syncthreads();

    // scatter: 128 rows x 16 float4 into this half's Z1 columns
    #pragma unroll
    for (int idx = tid; idx < 2048; idx += 256) {
        int r = idx >> 4, cc = idx & 15;
        int g = GID[r];
        if (g >= 0) {
            float4 v = *reinterpret_cast<const float4*>(HS + r * 68 + cc * 4);
            red4(&g_Z1[(size_t)g * HIDDEN + half * 64 + cc * 4], v);
        }
    }
}

// ---------------- readout GEMM (unchanged from R6/R10) ----------------
#define G_STAGE_FL (128*36 + 128*36)
#define SMEM_GRAPHS_FL (3*G_STAGE_FL + 128 + 128)
#define SMEM_GRAPHS_BYTES (SMEM_GRAPHS_FL * 4)

__global__ __launch_bounds__(256, 2)
void k_graphs(const float* __restrict__ gx, const float* __restrict__ W3,
              const float* __restrict__ b3, float* __restrict__ out) {
    extern __shared__ float smem[];
    float* SS  = smem + 3 * G_STAGE_FL;
    float* B3S = SS + 128;

    const int tid = threadIdx.x;
    const int lane = tid & 31;
    const int wid = tid >> 5;
    const int wm = wid >> 2;
    const int wn = wid & 3;
    const int g0 = blockIdx.x * 128;

    auto issue = [&](int kc, int buf) {
        float* ZSb = smem + buf * G_STAGE_FL;
        float* WSb = ZSb + 128 * 36;
        #pragma unroll
        for (int p = 0; p < 4; ++p) {
            int idx = p * 256 + tid;
            int r = idx >> 3, c4 = idx & 7;
            int g = g0 + r;
            unsigned sz = (g < N_GRAPHS) ? 16u : 0u;
            int gc = (g < N_GRAPHS) ? g : (N_GRAPHS - 1);
            const float* src;
            if (kc < 4)      src = g_Z1 + (size_t)gc * HIDDEN + kc * 32 + c4 * 4;
            else if (kc < 8) src = g_Z1 + (size_t)gc * HIDDEN + (kc - 4) * 32 + c4 * 4;
            else             src = gx + (size_t)gc * GDIM + (kc - 8) * 32 + c4 * 4;
            cp16(s2u(ZSb + r * 36 + c4 * 4), src, sz);
        }
        #pragma unroll
        for (int p = 0; p < 4; ++p) {
            int idx = p * 256 + tid;
            int j = idx >> 3, c4 = idx & 7;
            cp16(s2u(WSb + j * 36 + c4 * 4),
                 W3 + (size_t)j * 320 + kc * 32 + c4 * 4, 16u);
        }
        cp_commit();
    };

    issue(0, 0);
    issue(1, 1);

    if (tid < 128) {
        int g = g0 + tid;
        float cn = (g < N_GRAPHS) ? g_cnt[g] : 1.0f;
        SS[tid] = 1.0f / fmaxf(cn, 1.0f);
        B3S[tid] = b3[tid];
    }

    float c[4][4][4];
    #pragma unroll
    for (int mi = 0; mi < 4; ++mi)
        #pragma unroll
        for (int ni = 0; ni < 4; ++ni)
            #pragma unroll
            for (int q = 0; q < 4; ++q) c[mi][ni][q] = 0.f;

    const int ro = lane >> 2;
    const int col0 = lane & 3;

    for (int kc = 0; kc < 10; ++kc) {
        if (kc < 9) cp_wait<1>(); else cp_wait<0>();
        __syncthreads();

        const float* ZSf = smem + (kc % 3) * G_STAGE_FL;
        const float* WSf = ZSf + 128 * 36;
        const bool isZ2 = (kc >= 4) && (kc < 8);

        float s0[4], s1[4];
        #pragma unroll
        for (int mi = 0; mi < 4; ++mi) {
            int rb = wm * 64 + mi * 16;
            s0[mi] = isZ2 ? SS[rb + ro]     : 1.0f;
            s1[mi] = isZ2 ? SS[rb + ro + 8] : 1.0f;
        }

        #pragma unroll
        for (int ks = 0; ks < 4; ++ks) {
            const int co = ks * 8 + col0;
            unsigned a[4][4];
            #pragma unroll
            for (int mi = 0; mi < 4; ++mi) {
                int rb = wm * 64 + mi * 16;
                a[mi][0] = f2tf(ZSf[(rb + ro) * 36 + co]     * s0[mi]);
                a[mi][1] = f2tf(ZSf[(rb + ro + 8) * 36 + co] * s1[mi]);
                a[mi][2] = f2tf(ZSf[(rb + ro) * 36 + co + 4]     * s0[mi]);
                a[mi][3] = f2tf(ZSf[(rb + ro + 8) * 36 + co + 4] * s1[mi]);
            }
            #pragma unroll
            for (int ni = 0; ni < 4; ++ni) {
                int nr = wn * 32 + ni * 8 + ro;
                unsigned bb0 = f2tf(WSf[nr * 36 + co]);
                unsigned bb1 = f2tf(WSf[nr * 36 + co + 4]);
                #pragma unroll
                for (int mi = 0; mi < 4; ++mi)
                    mma_tf32(c[mi][ni][0], c[mi][ni][1], c[mi][ni][2], c[mi][ni][3],
                             a[mi][0], a[mi][1], a[mi][2], a[mi][3], bb0, bb1);
            }
        }

        if (kc + 2 <= 9) issue(kc + 2, (kc + 2) % 3);
    }

    #pragma unroll
    for (int mi = 0; mi < 4; ++mi) {
        #pragma unroll
        for (int ni = 0; ni < 4; ++ni) {
            int r = wm * 64 + mi * 16 + ro;
            int n = wn * 32 + ni * 8 + 2 * col0;
            int g = g0 + r;
            if (g < N_GRAPHS) {
                float2 v;
                v.x = fmaxf(c[mi][ni][0] + B3S[n], 0.f);
                v.y = fmaxf(c[mi][ni][1] + B3S[n + 1], 0.f);
                *reinterpret_cast<float2*>(out + (size_t)g * 128 + n) = v;
            }
            int g2 = g0 + r + 8;
            if (g2 < N_GRAPHS) {
                float2 v;
                v.x = fmaxf(c[mi][ni][2] + B3S[n], 0.f);
                v.y = fmaxf(c[mi][ni][3] + B3S[n + 1], 0.f);
                *reinterpret_cast<float2*>(out + (size_t)g2 * 128 + n) = v;
            }
        }
    }
}

// ---------------- launch ----------------
extern "C" void kernel_launch(void* const* d_in, const int* in_sizes, int n_in,
                              void* d_out, int out_size) {
    const float* x  = (const float*)d_in[0];
    const void*  n2g = d_in[1];
    const float* gx = (const float*)d_in[2];
    const float* W1 = (const float*)d_in[3];
    const float* b1 = (const float*)d_in[4];
    const float* W2 = (const float*)d_in[5];
    const float* b2 = (const float*)d_in[6];
    const float* W3 = (const float*)d_in[7];
    const float* b3 = (const float*)d_in[8];
    float* out = (float*)d_out;

    static bool attr_set = false;
    if (!attr_set) {
        cudaFuncSetAttribute(k_nodes, cudaFuncAttributeMaxDynamicSharedMemorySize,
                             SMEM_NODES_BYTES);
        cudaFuncSetAttribute(k_graphs, cudaFuncAttributeMaxDynamicSharedMemorySize,
                             SMEM_GRAPHS_BYTES);
        attr_set = true;
    }

    // launch order steers ncu (-s 5 -c 1): 4th launch captured -> k_nodes
    k_init<<<2048, 256>>>((const unsigned*)n2g, W1, W2);
    k_pad<<<1, 32>>>();
    k_pad<<<1, 32>>>();
    k_nodes<<<NT_TILES * 2, 256, SMEM_NODES_BYTES>>>(x, n2g, b1, b2);
    k_graphs<<<(N_GRAPHS + 127) / 128, 256, SMEM_GRAPHS_BYTES>>>(gx, W3, b3, out);
}

// round 17
// speedup vs baseline: 1.0001x; 1.0001x over previous
#include <cuda_runtime.h>
#include <cstdint>

#define V_NODES   1000000
#define N_GRAPHS  50000
#define NODE_DIM  128
#define HIDDEN    128
#define GDIM      64
#define NT_TILES  7813

// ---------------- scratch ----------------
__device__ __align__(256)  float g_Z1[(size_t)N_GRAPHS * HIDDEN];
__device__ __align__(256)  float g_cnt[N_GRAPHS];
__device__ __align__(1024) unsigned char g_Wq[131072];   // W quads, consume-order, XOR-swizzled
__device__ __align__(256)  unsigned g_W3tf[128 * 320];   // W3 pre-converted tf32 bits
__device__ int g_is64;

// ---------------- helpers ----------------
__device__ __forceinline__ unsigned f2tf(float f) {
    unsigned u; asm("cvt.rna.tf32.f32 %0, %1;" : "=r"(u) : "f"(f)); return u;
}
__device__ __forceinline__ void mma_tf32(float& c0, float& c1, float& c2, float& c3,
                                         unsigned a0, unsigned a1, unsigned a2, unsigned a3,
                                         unsigned b0, unsigned b1) {
    asm volatile(
        "mma.sync.aligned.m16n8k8.row.col.f32.tf32.tf32.f32 "
        "{%0,%1,%2,%3},{%4,%5,%6,%7},{%8,%9},{%0,%1,%2,%3};"
        : "+f"(c0), "+f"(c1), "+f"(c2), "+f"(c3)
        : "r"(a0), "r"(a1), "r"(a2), "r"(a3), "r"(b0), "r"(b1));
}
__device__ __forceinline__ void red4(float* p, float4 v) {
    asm volatile("red.global.add.v4.f32 [%0], {%1,%2,%3,%4};"
                 :: "l"(p), "f"(v.x), "f"(v.y), "f"(v.z), "f"(v.w) : "memory");
}
__device__ __forceinline__ float sigm(float x) { return 1.0f / (1.0f + __expf(-x)); }
__device__ __forceinline__ unsigned s2u(const void* p) {
    return (unsigned)__cvta_generic_to_shared(p);
}
__device__ __forceinline__ void cp16(unsigned d, const void* s, unsigned sz) {
    asm volatile("cp.async.cg.shared.global [%0], [%1], 16, %2;" :: "r"(d), "l"(s), "r"(sz));
}
__device__ __forceinline__ void cp_commit() { asm volatile("cp.async.commit_group;"); }
template <int N> __device__ __forceinline__ void cp_wait() {
    asm volatile("cp.async.wait_group %0;" :: "n"(N));
}

// ---------------- k_init: zero + detect + W quad pre-permute + W3 pre-convert ------
// W rows n: n=2j -> W1[j], n=2j+1 -> W2[j].
// Quad for (half, wn, kseg, lane, ni2) = (W[na][co], W[na][co+4], W[nb][co], W[nb][co+4])
//   na = half*128 + wn*64 + 2*ni2*8 + ro, nb = na+8, co = kseg*8 + col0
// stored at half*65536 + wn*32768 + kseg*2048 + lane*64 + (ni2^((lane>>1)&3))*16.
__global__ void k_init(const unsigned* __restrict__ n2g_words,
                       const float* __restrict__ W1, const float* __restrict__ W2,
                       const float* __restrict__ W3) {
    if (blockIdx.x == 0) {
        __shared__ int nz;
        if (threadIdx.x == 0) nz = 0;
        __syncthreads();
        unsigned acc = 0;
        #pragma unroll
        for (int q = 0; q < 4; ++q) acc |= n2g_words[2 * (threadIdx.x * 4 + q) + 1];
        if (acc != 0u) atomicOr(&nz, 1);
        __syncthreads();
        if (threadIdx.x == 0) g_is64 = (nz == 0) ? 1 : 0;
    }
    size_t i = (size_t)blockIdx.x * blockDim.x + threadIdx.x;
    size_t st = (size_t)gridDim.x * blockDim.x;

    for (size_t q = i; q < 8192; q += st) {
        int half = (int)(q >> 12);
        int wn   = (int)((q >> 11) & 1);
        int kseg = (int)((q >> 7) & 15);
        int lane = (int)((q >> 2) & 31);
        int ni2  = (int)(q & 3);
        int ro = lane >> 2, col0 = lane & 3;
        int co = kseg * 8 + col0;
        int na = half * 128 + wn * 64 + 2 * ni2 * 8 + ro;
        int nb = na + 8;
        const float* sa = (na & 1) ? W2 : W1;
        const float* sb = (nb & 1) ? W2 : W1;
        uint4 u = make_uint4(f2tf(sa[(na >> 1) * 128 + co]),
                             f2tf(sa[(na >> 1) * 128 + co + 4]),
                             f2tf(sb[(nb >> 1) * 128 + co]),
                             f2tf(sb[(nb >> 1) * 128 + co + 4]));
        unsigned off = (unsigned)(half * 65536 + wn * 32768 + kseg * 2048
                                  + lane * 64 + (ni2 ^ ((lane >> 1) & 3)) * 16);
        *reinterpret_cast<uint4*>(g_Wq + off) = u;
    }

    for (size_t k = i; k < 128 * 320; k += st) g_W3tf[k] = f2tf(W3[k]);

    float4* z = reinterpret_cast<float4*>(g_Z1);
    const size_t n4 = (size_t)N_GRAPHS * HIDDEN / 4;
    for (size_t k = i; k < n4; k += st) z[k] = make_float4(0.f, 0.f, 0.f, 0.f);
    for (size_t k = i; k < N_GRAPHS; k += st) g_cnt[k] = 0.f;
}

__global__ void k_pad() {}

// ---------------- k_nodes: split-N gated MLP + scatter (R11 + W quads) ----------------
// blockIdx = tile*2 + half. 256 thr = 8 warps, 4(m) x 2(n), warp tile 32x64.
// W-half resident as quads (LDS.128, XOR-swizzled, conflict-free). X: 2-stage cp.async.
#define WQ_BYTES 65536                   // resident W half
#define WT_FLH   (WQ_BYTES / 4)
#define XSTG_FL  (128 * 36)              // one X stage (18432 B)
#define HS_FL    (128 * 68)
#define SMEM_NODES_FL (WT_FLH + 2*XSTG_FL + 64 + 64 + 128)
#define SMEM_NODES_BYTES (SMEM_NODES_FL * 4)   // 103,424 B -> 2 CTA/SM

__global__ __launch_bounds__(256, 2)
void k_nodes(const float* __restrict__ x, const void* __restrict__ n2g,
             const float* __restrict__ b1, const float* __restrict__ b2) {
    extern __shared__ float smem[];
    char*  WQ  = reinterpret_cast<char*>(smem);         // [65536] quads
    float* XS  = smem + WT_FLH;                          // [2][128*36]
    float* HS  = smem + WT_FLH;                          // aliases X stages after drain
    float* B1S = smem + WT_FLH + 2 * XSTG_FL;
    float* B2S = B1S + 64;
    int*   GID = reinterpret_cast<int*>(B2S + 64);

    const int tid = threadIdx.x;
    const int lane = tid & 31;
    const int wid = tid >> 5;
    const int wm = wid >> 1;
    const int wn = wid & 1;
    const int tile = blockIdx.x >> 1;
    const int half = blockIdx.x & 1;
    const int node0 = tile * 128;
    const int is64 = g_is64;

    // group 0: resident W quads (4096 x 16B)
    const char* wsrc = reinterpret_cast<const char*>(g_Wq) + half * WQ_BYTES;
    #pragma unroll
    for (int p = 0; p < 16; ++p) {
        int idx = p * 256 + tid;
        cp16(s2u(WQ + idx * 16), wsrc + idx * 16, 16u);
    }
    cp_commit();

    auto issueX = [&](int kc, int buf) {
        float* XSb = XS + buf * XSTG_FL;
        #pragma unroll
        for (int p = 0; p < 4; ++p) {
            int idx = p * 256 + tid;
            int r = idx >> 3, c4 = idx & 7;
            int node = node0 + r;
            unsigned sz = (node < V_NODES) ? 16u : 0u;
            int nc = (node < V_NODES) ? node : (V_NODES - 1);
            cp16(s2u(XSb + r * 36 + c4 * 4),
                 x + (size_t)nc * NODE_DIM + kc * 32 + c4 * 4, sz);
        }
        cp_commit();
    };

    issueX(0, 0);
    issueX(1, 1);

    if (tid < 64)        B1S[tid]      = b1[half * 64 + tid];
    else if (tid < 128)  B2S[tid - 64] = b2[half * 64 + tid - 64];
    if (tid < 128) {
        int node = node0 + tid;
        int g = -1;
        if (node < V_NODES) {
            g = is64 ? (int)reinterpret_cast<const long long*>(n2g)[node]
                     : reinterpret_cast<const int*>(n2g)[node];
            if (half == 0) atomicAdd(&g_cnt[g], 1.0f);
        }
        GID[tid] = g;
    }

    float c[2][8][4];
    #pragma unroll
    for (int mi = 0; mi < 2; ++mi)
        #pragma unroll
        for (int ni = 0; ni < 8; ++ni)
            #pragma unroll
            for (int q = 0; q < 4; ++q) c[mi][ni][q] = 0.f;

    const int ro = lane >> 2;
    const int col0 = lane & 3;
    const int lsw = (lane >> 1) & 3;
    // per-lane W base (within wn segment): lane*64
    const char* WQl = WQ + wn * 32768 + lane * 64;

    #pragma unroll
    for (int kc = 0; kc < 4; ++kc) {
        if (kc < 3) cp_wait<1>(); else cp_wait<0>();
        __syncthreads();

        const float* XSf = XS + (kc & 1) * XSTG_FL;
        #pragma unroll
        for (int ks = 0; ks < 4; ++ks) {
            const int co = ks * 8 + col0;
            unsigned a[2][4];
            #pragma unroll
            for (int mi = 0; mi < 2; ++mi) {
                int rb = wm * 32 + mi * 16;
                a[mi][0] = f2tf(XSf[(rb + ro) * 36 + co]);
                a[mi][1] = f2tf(XSf[(rb + ro + 8) * 36 + co]);
                a[mi][2] = f2tf(XSf[(rb + ro) * 36 + co + 4]);
                a[mi][3] = f2tf(XSf[(rb + ro + 8) * 36 + co + 4]);
            }
            const char* wseg = WQl + (kc * 4 + ks) * 2048;
            #pragma unroll
            for (int ni2 = 0; ni2 < 4; ++ni2) {
                uint4 wq = *reinterpret_cast<const uint4*>(wseg + ((ni2 ^ lsw) << 4));
                // ni = 2*ni2   : b = (wq.x, wq.y)
                mma_tf32(c[0][2*ni2][0], c[0][2*ni2][1], c[0][2*ni2][2], c[0][2*ni2][3],
                         a[0][0], a[0][1], a[0][2], a[0][3], wq.x, wq.y);
                mma_tf32(c[1][2*ni2][0], c[1][2*ni2][1], c[1][2*ni2][2], c[1][2*ni2][3],
                         a[1][0], a[1][1], a[1][2], a[1][3], wq.x, wq.y);
                // ni = 2*ni2+1 : b = (wq.z, wq.w)
                mma_tf32(c[0][2*ni2+1][0], c[0][2*ni2+1][1], c[0][2*ni2+1][2], c[0][2*ni2+1][3],
                         a[0][0], a[0][1], a[0][2], a[0][3], wq.z, wq.w);
                mma_tf32(c[1][2*ni2+1][0], c[1][2*ni2+1][1], c[1][2*ni2+1][2], c[1][2*ni2+1][3],
                         a[1][0], a[1][1], a[1][2], a[1][3], wq.z, wq.w);
            }
        }

        __syncthreads();
        if (kc + 2 <= 3) issueX(kc + 2, kc & 1);
    }

    // epilogue: gate -> HS half (C col pairs: even=lin1[j], odd=lin2[j])
    #pragma unroll
    for (int ni = 0; ni < 8; ++ni) {
        int j = wn * 32 + ni * 4 + col0;
        float bb1 = B1S[j], bb2 = B2S[j];
        int r = wm * 32 + ro;
        HS[r * 68 + j]        = (c[0][ni][0] + bb1) * sigm(c[0][ni][1] + bb2);
        HS[(r + 8) * 68 + j]  = (c[0][ni][2] + bb1) * sigm(c[0][ni][3] + bb2);
        HS[(r + 16) * 68 + j] = (c[1][ni][0] + bb1) * sigm(c[1][ni][1] + bb2);
        HS[(r + 24) * 68 + j] = (c[1][ni][2] + bb1) * sigm(c[1][ni][3] + bb2);
    }
    __syncthreads();

    // scatter: 128 rows x 16 float4 into this half's Z1 columns
    #pragma unroll
    for (int idx = tid; idx < 2048; idx += 256) {
        int r = idx >> 4, cc = idx & 15;
        int g = GID[r];
        if (g >= 0) {
            float4 v = *reinterpret_cast<const float4*>(HS + r * 68 + cc * 4);
            red4(&g_Z1[(size_t)g * HIDDEN + half * 64 + cc * 4], v);
        }
    }
}

// ---------------- k_graphs: readout GEMM (R11 + preconverted W3) ----------------
#define G_STAGE_FL (128*36 + 128*36)
#define SMEM_GRAPHS_BYTES ((3*G_STAGE_FL + 256) * 4)

__global__ __launch_bounds__(256, 2)
void k_graphs(const float* __restrict__ gx, const float* __restrict__ b3,
              float* __restrict__ out) {
    extern __shared__ float smem[];
    float* SS  = smem + 3 * G_STAGE_FL;
    float* B3S = SS + 128;
    const int tid = threadIdx.x, lane = tid & 31, wid = tid >> 5;
    const int wm = wid >> 2, wn = wid & 3;
    const int g0 = blockIdx.x * 128;

    auto issue = [&](int kc, int buf) {
        float* ZSb = smem + buf * G_STAGE_FL;
        float* WSb = ZSb + 128 * 36;
        #pragma unroll
        for (int p = 0; p < 4; ++p) {
            int idx = p * 256 + tid;
            int r = idx >> 3, c4 = idx & 7;
            int g = g0 + r;
            unsigned sz = (g < N_GRAPHS) ? 16u : 0u;
            int gc = (g < N_GRAPHS) ? g : (N_GRAPHS - 1);
            const float* src;
            if (kc < 4)      src = g_Z1 + (size_t)gc * HIDDEN + kc * 32 + c4 * 4;
            else if (kc < 8) src = g_Z1 + (size_t)gc * HIDDEN + (kc - 4) * 32 + c4 * 4;
            else             src = gx + (size_t)gc * GDIM + (kc - 8) * 32 + c4 * 4;
            cp16(s2u(ZSb + r * 36 + c4 * 4), src, sz);
        }
        #pragma unroll
        for (int p = 0; p < 4; ++p) {
            int idx = p * 256 + tid;
            int j = idx >> 3, c4 = idx & 7;
            cp16(s2u(WSb + j * 36 + c4 * 4),
                 g_W3tf + (size_t)j * 320 + kc * 32 + c4 * 4, 16u);
        }
        cp_commit();
    };

    issue(0, 0);
    issue(1, 1);
    if (tid < 128) {
        int g = g0 + tid;
        float cn = (g < N_GRAPHS) ? g_cnt[g] : 1.0f;
        SS[tid] = 1.0f / fmaxf(cn, 1.0f);
        B3S[tid] = b3[tid];
    }

    float c[4][4][4];
    #pragma unroll
    for (int mi = 0; mi < 4; ++mi)
        #pragma unroll
        for (int ni = 0; ni < 4; ++ni)
            #pragma unroll
            for (int q = 0; q < 4; ++q) c[mi][ni][q] = 0.f;

    const int ro = lane >> 2, col0 = lane & 3;
    for (int kc = 0; kc < 10; ++kc) {
        if (kc < 9) cp_wait<1>(); else cp_wait<0>();
        __syncthreads();
        const float* ZSf = smem + (kc % 3) * G_STAGE_FL;
        const unsigned* WSu = reinterpret_cast<const unsigned*>(ZSf + 128 * 36);
        const bool isZ2 = (kc >= 4) && (kc < 8);
        float s0[4], s1[4];
        #pragma unroll
        for (int mi = 0; mi < 4; ++mi) {
            int rb = wm * 64 + mi * 16;
            s0[mi] = isZ2 ? SS[rb + ro] : 1.0f;
            s1[mi] = isZ2 ? SS[rb + ro + 8] : 1.0f;
        }
        #pragma unroll
        for (int ks = 0; ks < 4; ++ks) {
            const int co = ks * 8 + col0;
            unsigned a[4][4];
            #pragma unroll
            for (int mi = 0; mi < 4; ++mi) {
                int rb = wm * 64 + mi * 16;
                a[mi][0] = f2tf(ZSf[(rb + ro) * 36 + co]     * s0[mi]);
                a[mi][1] = f2tf(ZSf[(rb + ro + 8) * 36 + co] * s1[mi]);
                a[mi][2] = f2tf(ZSf[(rb + ro) * 36 + co + 4]     * s0[mi]);
                a[mi][3] = f2tf(ZSf[(rb + ro + 8) * 36 + co + 4] * s1[mi]);
            }
            #pragma unroll
            for (int ni = 0; ni < 4; ++ni) {
                int nr = wn * 32 + ni * 8 + ro;
                unsigned bb0 = WSu[nr * 36 + co];
                unsigned bb1 = WSu[nr * 36 + co + 4];
                #pragma unroll
                for (int mi = 0; mi < 4; ++mi)
                    mma_tf32(c[mi][ni][0], c[mi][ni][1], c[mi][ni][2], c[mi][ni][3],
                             a[mi][0], a[mi][1], a[mi][2], a[mi][3], bb0, bb1);
            }
        }
        if (kc + 2 <= 9) issue(kc + 2, (kc + 2) % 3);
    }

    #pragma unroll
    for (int mi = 0; mi < 4; ++mi)
        #pragma unroll
        for (int ni = 0; ni < 4; ++ni) {
            int r = wm * 64 + mi * 16 + ro;
            int n = wn * 32 + ni * 8 + 2 * col0;
            int g = g0 + r;
            if (g < N_GRAPHS) {
                float2 v;
                v.x = fmaxf(c[mi][ni][0] + B3S[n], 0.f);
                v.y = fmaxf(c[mi][ni][1] + B3S[n + 1], 0.f);
                *reinterpret_cast<float2*>(out + (size_t)g * 128 + n) = v;
            }
            int g2 = g0 + r + 8;
            if (g2 < N_GRAPHS) {
                float2 v;
                v.x = fmaxf(c[mi][ni][2] + B3S[n], 0.f);
                v.y = fmaxf(c[mi][ni][3] + B3S[n + 1], 0.f);
                *reinterpret_cast<float2*>(out + (size_t)g2 * 128 + n) = v;
            }
        }
}

// ---------------- launch ----------------
extern "C" void kernel_launch(void* const* d_in, const int* in_sizes, int n_in,
                              void* d_out, int out_size) {
    const float* x  = (const float*)d_in[0];
    const void*  n2g = d_in[1];
    const float* gx = (const float*)d_in[2];
    const float* W1 = (const float*)d_in[3];
    const float* b1 = (const float*)d_in[4];
    const float* W2 = (const float*)d_in[5];
    const float* b2 = (const float*)d_in[6];
    const float* W3 = (const float*)d_in[7];
    const float* b3 = (const float*)d_in[8];
    float* out = (float*)d_out;

    static bool attr_set = false;
    if (!attr_set) {
        cudaFuncSetAttribute(k_nodes, cudaFuncAttributeMaxDynamicSharedMemorySize,
                             SMEM_NODES_BYTES);
        cudaFuncSetAttribute(k_graphs, cudaFuncAttributeMaxDynamicSharedMemorySize,
                             SMEM_GRAPHS_BYTES);
        attr_set = true;
    }

    // launch order steers ncu (-s 5 -c 1): 4th launch captured -> k_nodes
    k_init<<<2048, 256>>>((const unsigned*)n2g, W1, W2, W3);
    k_pad<<<1, 32>>>();
    k_pad<<<1, 32>>>();
    k_nodes<<<NT_TILES * 2, 256, SMEM_NODES_BYTES>>>(x, n2g, b1, b2);
    k_graphs<<<(N_GRAPHS + 127) / 128, 256, SMEM_GRAPHS_BYTES>>>(gx, b3, out);
}